// round 3
// baseline (speedup 1.0000x reference)
#include <cuda_runtime.h>
#include <math.h>

#define NN   30000
#define E1   400000
#define C1N  15000
#define E2N  100000
#define C2N  7500
#define NBAT 16

// ---------------- scratch (__device__ globals; no dynamic alloc) ----------------
__device__ int      g_cnt_dst1[NN];
__device__ int      g_off1[NN];
__device__ int      g_cur1[NN];
__device__ int      g_elist1[E1];
__device__ int      g_cnt_c1[C1N];
__device__ int      g_cnt_dst2[C1N];
__device__ int      g_off2[C1N];
__device__ int      g_cur2[C1N];
__device__ int      g_elist2[E2N];
__device__ float    g_possum[C1N * 3];
__device__ int      g_batchp[C1N];
__device__ unsigned g_xp_u[C1N * 32];
__device__ float    g_xp[C1N * 32];
__device__ float    g_A1[NN * 162];
__device__ float    g_W1p[162 * 32];
__device__ float    g_cart[E2N * 3];
__device__ unsigned g_absmax;
__device__ float    g_A2[C1N * 864];
__device__ float    g_W2p[864 * 64];
__device__ unsigned g_x3_u[C2N * 64];
__device__ int      g_batch2[C2N];
__device__ float    g_gsum[NBAT * 64];
__device__ int      g_cntb[NBAT];

// order-preserving float <-> uint so atomicMax works; 0u == "empty" decodes to 0.0f
__device__ __forceinline__ unsigned fenc(float f) {
    unsigned u = __float_as_uint(f);
    return (u & 0x80000000u) ? ~u : (u | 0x80000000u);
}
__device__ __forceinline__ float fdec(unsigned u) {
    if (u == 0u) return 0.f;
    return (u & 0x80000000u) ? __uint_as_float(u & 0x7FFFFFFFu) : __uint_as_float(~u);
}
__device__ __forceinline__ float elu_f(float x) {
    return x > 0.f ? x : (expf(x) - 1.f);
}

// ---------------- init ----------------
__global__ void k_zero() {
    int t = blockIdx.x * blockDim.x + threadIdx.x;
    int S = gridDim.x * blockDim.x;
    for (int i = t; i < C1N * 32; i += S) g_xp_u[i] = 0u;
    for (int i = t; i < C2N * 64; i += S) g_x3_u[i] = 0u;
    for (int i = t; i < C1N * 3;  i += S) g_possum[i] = 0.f;
    for (int i = t; i < NN;       i += S) g_cnt_dst1[i] = 0;
    for (int i = t; i < C1N;      i += S) { g_cnt_c1[i] = 0; g_cnt_dst2[i] = 0; g_batchp[i] = 0; }
    for (int i = t; i < C2N;      i += S) g_batch2[i] = 0;
    for (int i = t; i < NBAT * 64;i += S) g_gsum[i] = 0.f;
    for (int i = t; i < NBAT;     i += S) g_cntb[i] = 0;
    if (t == 0) g_absmax = 0u;
}

// ---------------- degree counts + pos-sum + batchp ----------------
__global__ void k_count(const int* __restrict__ eidx, const int* __restrict__ eidx2,
                        const int* __restrict__ cl1, const int* __restrict__ batch,
                        const float* __restrict__ pos) {
    int t = blockIdx.x * blockDim.x + threadIdx.x;
    int S = gridDim.x * blockDim.x;
    for (int e = t; e < E1;  e += S) atomicAdd(&g_cnt_dst1[eidx[E1 + e]], 1);
    for (int e = t; e < E2N; e += S) atomicAdd(&g_cnt_dst2[eidx2[E2N + e]], 1);
    for (int n = t; n < NN;  n += S) {
        int c = cl1[n];
        atomicAdd(&g_cnt_c1[c], 1);
        atomicAdd(&g_possum[c * 3 + 0], pos[n * 3 + 0]);
        atomicAdd(&g_possum[c * 3 + 1], pos[n * 3 + 1]);
        atomicAdd(&g_possum[c * 3 + 2], pos[n * 3 + 2]);
        atomicMax(&g_batchp[c], batch[n]);
    }
}

// ---------------- single-block exclusive scan -> CSR offsets ----------------
__global__ void k_scan(const int* __restrict__ cnt, int* __restrict__ off,
                       int* __restrict__ cur, int n) {
    __shared__ int part[1024];
    int t = threadIdx.x;
    int chunk = (n + 1023) / 1024;
    int lo = t * chunk, hi = min(lo + chunk, n);
    int s = 0;
    for (int i = lo; i < hi; i++) s += cnt[i];
    part[t] = s;
    __syncthreads();
    for (int d = 1; d < 1024; d <<= 1) {
        int v = (t >= d) ? part[t - d] : 0;
        __syncthreads();
        part[t] += v;
        __syncthreads();
    }
    int run = (t == 0) ? 0 : part[t - 1];
    for (int i = lo; i < hi; i++) { off[i] = run; cur[i] = run; run += cnt[i]; }
}

// ---------------- fill CSR edge lists ----------------
__global__ void k_fill(const int* __restrict__ eidx, const int* __restrict__ eidx2) {
    int t = blockIdx.x * blockDim.x + threadIdx.x;
    int S = gridDim.x * blockDim.x;
    for (int e = t; e < E1; e += S) {
        int d = eidx[E1 + e];
        int p = atomicAdd(&g_cur1[d], 1);
        g_elist1[p] = e;
    }
    for (int e = t; e < E2N; e += S) {
        int d = eidx2[E2N + e];
        int p = atomicAdd(&g_cur2[d], 1);
        g_elist2[p] = e;
    }
}

// ---------------- repack fused weights ----------------
// W1p[j,o], j=i*26+k (i<6,k<26): k<25 -> w1b[k,i*32+o], k==25 -> b1b[i*32+o];
//           j in [156,162): root1[j-156, o]
// W2p[j,o], j=k*32+i (k<26,i<32): k<25 -> w2b[k,i*64+o], k==25 -> b2b[i*64+o];
//           j in [832,864): root2[j-832, o]
__global__ void k_repack(const float* __restrict__ w1b, const float* __restrict__ b1b,
                         const float* __restrict__ root1,
                         const float* __restrict__ w2b, const float* __restrict__ b2b,
                         const float* __restrict__ root2) {
    int t = blockIdx.x * blockDim.x + threadIdx.x;
    int S = gridDim.x * blockDim.x;
    for (int idx = t; idx < 162 * 32; idx += S) {
        int j = idx >> 5, o = idx & 31;
        float v;
        if (j < 156) {
            int i = j / 26, k = j % 26;
            v = (k < 25) ? w1b[k * 192 + i * 32 + o] : b1b[i * 32 + o];
        } else {
            v = root1[(j - 156) * 32 + o];
        }
        g_W1p[idx] = v;
    }
    for (int idx = t; idx < 864 * 64; idx += S) {
        int j = idx >> 6, o = idx & 63;
        float v;
        if (j < 832) {
            int k = j >> 5, i = j & 31;
            v = (k < 25) ? w2b[k * 2048 + i * 64 + o] : b2b[i * 64 + o];
        } else {
            v = root2[(j - 832) * 64 + o];
        }
        g_W2p[idx] = v;
    }
}

// ---------------- conv1 edge accumulation: one warp per destination node ----------------
__global__ void k_conv1(const float* __restrict__ x, const float* __restrict__ eattr,
                        const int* __restrict__ eidx,
                        const float* __restrict__ w1a, const float* __restrict__ b1a) {
    int wg = (blockIdx.x * blockDim.x + threadIdx.x) >> 5;
    int lane = threadIdx.x & 31;
    if (wg >= NN) return;
    int n = wg;
    float wa0 = 0.f, wa1 = 0.f, wa2 = 0.f, ba = 0.f;
    if (lane < 25) { wa0 = w1a[lane]; wa1 = w1a[25 + lane]; wa2 = w1a[50 + lane]; ba = b1a[lane]; }
    int it[5], kt[5]; bool vt[5];
#pragma unroll
    for (int t = 0; t < 5; t++) {
        int f = lane + 32 * t;
        vt[t] = (f < 156);
        int ff = vt[t] ? f : 0;
        it[t] = ff / 26; kt[t] = ff % 26;
    }
    float acc[5] = {0.f, 0.f, 0.f, 0.f, 0.f};
    int off = g_off1[n], deg = g_cnt_dst1[n];
    for (int q = 0; q < deg; q++) {
        int e = g_elist1[off + q];
        int s = eidx[e];  // src
        float xr = (lane < 6) ? x[s * 6 + lane] : 0.f;
        float er = (lane < 3) ? eattr[e * 3 + lane] : 0.f;
        float a0 = __shfl_sync(0xffffffffu, er, 0);
        float a1 = __shfl_sync(0xffffffffu, er, 1);
        float a2 = __shfl_sync(0xffffffffu, er, 2);
        float h;
        if (lane < 25) {
            h = fmaf(a2, wa2, fmaf(a1, wa1, fmaf(a0, wa0, ba)));
            h = h > 0.f ? h : 0.f;
        } else {
            h = (lane == 25) ? 1.f : 0.f;
        }
#pragma unroll
        for (int t = 0; t < 5; t++) {
            float xv = __shfl_sync(0xffffffffu, xr, it[t]);
            float hv = __shfl_sync(0xffffffffu, h, kt[t]);
            if (vt[t]) acc[t] = fmaf(xv, hv, acc[t]);
        }
    }
    float inv = 1.f / (float)max(deg, 1);
    float* Arow = &g_A1[n * 162];
#pragma unroll
    for (int t = 0; t < 5; t++) {
        int f = lane + 32 * t;
        if (f < 156) Arow[f] = acc[t] * inv;
    }
    if (lane < 6) Arow[156 + lane] = x[n * 6 + lane];
}

// ---------------- GEMM1 [NN,162]@[162,32] + bias1, elu, pool1 atomicMax ----------------
__global__ void k_gemm1(const float* __restrict__ bias1, const int* __restrict__ cl1) {
    int warp = (blockIdx.x * blockDim.x + threadIdx.x) >> 5;
    int lane = threadIdx.x & 31;
    int n0 = warp * 4;
    if (n0 >= NN) return;
    int nr[4];
#pragma unroll
    for (int r = 0; r < 4; r++) nr[r] = min(n0 + r, NN - 1);
    float acc[4] = {0.f, 0.f, 0.f, 0.f};
    for (int kc = 0; kc < 162; kc += 32) {
        float a[4];
#pragma unroll
        for (int r = 0; r < 4; r++)
            a[r] = (kc + lane < 162) ? g_A1[nr[r] * 162 + kc + lane] : 0.f;
        int kmax = min(32, 162 - kc);
#pragma unroll 8
        for (int t = 0; t < kmax; t++) {
            float w = g_W1p[(kc + t) * 32 + lane];
#pragma unroll
            for (int r = 0; r < 4; r++)
                acc[r] = fmaf(__shfl_sync(0xffffffffu, a[r], t), w, acc[r]);
        }
    }
    float b = bias1[lane];
#pragma unroll
    for (int r = 0; r < 4; r++) {
        int n = n0 + r;
        if (n < NN) {
            float v = elu_f(acc[r] + b);
            atomicMax(&g_xp_u[cl1[n] * 32 + lane], fenc(v));
        }
    }
}

// ---------------- pool1 finalize: decode xp, pos mean, batch2 max ----------------
__global__ void k_pool1fin(const int* __restrict__ cl2) {
    int t = blockIdx.x * blockDim.x + threadIdx.x;
    int S = gridDim.x * blockDim.x;
    for (int i = t; i < C1N * 32; i += S) g_xp[i] = fdec(g_xp_u[i]);
    for (int c = t; c < C1N; c += S) {
        float inv = 1.f / (float)max(g_cnt_c1[c], 1);
        g_possum[c * 3 + 0] *= inv;
        g_possum[c * 3 + 1] *= inv;
        g_possum[c * 3 + 2] *= inv;
        atomicMax(&g_batch2[cl2[c]], g_batchp[c]);
    }
}

// ---------------- cartesian edge features + global abs-max ----------------
__global__ void k_cart(const int* __restrict__ eidx2) {
    int e = blockIdx.x * blockDim.x + threadIdx.x;
    float m = 0.f;
    if (e < E2N) {
        int s = eidx2[e], d = eidx2[E2N + e];
#pragma unroll
        for (int c = 0; c < 3; c++) {
            float v = g_possum[s * 3 + c] - g_possum[d * 3 + c];
            g_cart[e * 3 + c] = v;
            m = fmaxf(m, fabsf(v));
        }
    }
#pragma unroll
    for (int o = 16; o; o >>= 1) m = fmaxf(m, __shfl_xor_sync(0xffffffffu, m, o));
    if ((threadIdx.x & 31) == 0) atomicMax(&g_absmax, __float_as_uint(m));
}

// ---------------- conv2 edge accumulation: one warp per destination cluster ----------------
__global__ void k_conv2(const int* __restrict__ eidx2,
                        const float* __restrict__ w2a, const float* __restrict__ b2a) {
    int wg = (blockIdx.x * blockDim.x + threadIdx.x) >> 5;
    int lane = threadIdx.x & 31;
    if (wg >= C1N) return;
    int c = wg;
    float wa0 = 0.f, wa1 = 0.f, wa2 = 0.f, ba = 0.f;
    if (lane < 25) { wa0 = w2a[lane]; wa1 = w2a[25 + lane]; wa2 = w2a[50 + lane]; ba = b2a[lane]; }
    float scale = 0.5f / __uint_as_float(g_absmax);
    float acc[26];
#pragma unroll
    for (int k = 0; k < 26; k++) acc[k] = 0.f;
    int off = g_off2[c], deg = g_cnt_dst2[c];
    for (int q = 0; q < deg; q++) {
        int e = g_elist2[off + q];
        int s = eidx2[e];  // src
        float cr = (lane < 3) ? fmaf(g_cart[e * 3 + lane], scale, 0.5f) : 0.f;
        float a0 = __shfl_sync(0xffffffffu, cr, 0);
        float a1 = __shfl_sync(0xffffffffu, cr, 1);
        float a2 = __shfl_sync(0xffffffffu, cr, 2);
        float h;
        if (lane < 25) {
            h = fmaf(a2, wa2, fmaf(a1, wa1, fmaf(a0, wa0, ba)));
            h = h > 0.f ? h : 0.f;
        } else {
            h = (lane == 25) ? 1.f : 0.f;
        }
        float xv = g_xp[s * 32 + lane];
#pragma unroll
        for (int k = 0; k < 26; k++)
            acc[k] = fmaf(xv, __shfl_sync(0xffffffffu, h, k), acc[k]);
    }
    float inv = 1.f / (float)max(deg, 1);
    float* Arow = &g_A2[c * 864];
#pragma unroll
    for (int k = 0; k < 26; k++) Arow[k * 32 + lane] = acc[k] * inv;
    Arow[832 + lane] = g_xp[c * 32 + lane];
}

// ---------------- GEMM2 [C1,864]@[864,64] + bias2, elu, pool2 atomicMax ----------------
__global__ void k_gemm2(const float* __restrict__ bias2, const int* __restrict__ cl2) {
    int warp = (blockIdx.x * blockDim.x + threadIdx.x) >> 5;
    int lane = threadIdx.x & 31;
    int n0 = warp * 4;
    if (n0 >= C1N) return;
    int nr[4];
#pragma unroll
    for (int r = 0; r < 4; r++) nr[r] = min(n0 + r, C1N - 1);
    float acc0[4] = {0.f, 0.f, 0.f, 0.f};
    float acc1[4] = {0.f, 0.f, 0.f, 0.f};
    const float2* W2 = (const float2*)g_W2p;
    for (int kc = 0; kc < 864; kc += 32) {
        float a[4];
#pragma unroll
        for (int r = 0; r < 4; r++) a[r] = g_A2[nr[r] * 864 + kc + lane];
#pragma unroll 8
        for (int t = 0; t < 32; t++) {
            float2 w = W2[(kc + t) * 32 + lane];  // cols 2*lane, 2*lane+1
#pragma unroll
            for (int r = 0; r < 4; r++) {
                float av = __shfl_sync(0xffffffffu, a[r], t);
                acc0[r] = fmaf(av, w.x, acc0[r]);
                acc1[r] = fmaf(av, w.y, acc1[r]);
            }
        }
    }
    float b0 = bias2[2 * lane], b1 = bias2[2 * lane + 1];
#pragma unroll
    for (int r = 0; r < 4; r++) {
        int n = n0 + r;
        if (n < C1N) {
            float v0 = elu_f(acc0[r] + b0);
            float v1 = elu_f(acc1[r] + b1);
            int c2 = cl2[n];
            atomicMax(&g_x3_u[c2 * 64 + 2 * lane + 0], fenc(v0));
            atomicMax(&g_x3_u[c2 * 64 + 2 * lane + 1], fenc(v1));
        }
    }
}

// ---------------- pool2 -> per-batch sums ----------------
__global__ void k_pool2() {
    int t = blockIdx.x * blockDim.x + threadIdx.x;
    int S = gridDim.x * blockDim.x;
    for (int idx = t; idx < C2N * 64; idx += S) {
        float v = fdec(g_x3_u[idx]);
        int c2 = idx >> 6, o = idx & 63;
        int b = g_batch2[c2];
        atomicAdd(&g_gsum[b * 64 + o], v);
        if (o == 0) atomicAdd(&g_cntb[b], 1);
    }
}

// ---------------- head: mean -> fc1+elu -> fc2 -> log_softmax ----------------
__global__ void k_head(const float* __restrict__ fc1w, const float* __restrict__ fc1b,
                       const float* __restrict__ fc2w, const float* __restrict__ fc2b,
                       float* __restrict__ out) {
    __shared__ float sg[16 * 64];
    __shared__ float sh[16 * 128];
    __shared__ float sl[16 * 10];
    int t = threadIdx.x;
    for (int i = t; i < 16 * 64; i += 256) {
        int b = i >> 6;
        sg[i] = g_gsum[i] / (float)max(g_cntb[b], 1);
    }
    __syncthreads();
    for (int i = t; i < 16 * 128; i += 256) {
        int b = i >> 7, j = i & 127;
        float a = fc1b[j];
        for (int q = 0; q < 64; q++) a = fmaf(sg[b * 64 + q], fc1w[q * 128 + j], a);
        sh[i] = elu_f(a);
    }
    __syncthreads();
    for (int i = t; i < 160; i += 256) {
        int b = i / 10, j = i % 10;
        float a = fc2b[j];
        for (int q = 0; q < 128; q++) a = fmaf(sh[b * 128 + q], fc2w[q * 10 + j], a);
        sl[i] = a;
    }
    __syncthreads();
    if (t < 16) {
        float m = -1e30f;
        for (int j = 0; j < 10; j++) m = fmaxf(m, sl[t * 10 + j]);
        float s = 0.f;
        for (int j = 0; j < 10; j++) s += expf(sl[t * 10 + j] - m);
        float lse = logf(s);
        for (int j = 0; j < 10; j++) out[t * 10 + j] = sl[t * 10 + j] - m - lse;
    }
}

// ---------------- host launch ----------------
extern "C" void kernel_launch(void* const* d_in, const int* in_sizes, int n_in,
                              void* d_out, int out_size) {
    const float *x = 0, *ea = 0, *pos = 0, *w1a = 0, *b1a = 0, *w1b = 0, *b1b = 0,
                *root1 = 0, *bias1 = 0, *w2a = 0, *b2a = 0, *w2b = 0, *b2b = 0,
                *root2 = 0, *bias2 = 0, *fc1w = 0, *fc1b = 0, *fc2w = 0, *fc2b = 0;
    const int *eidx = 0, *batch = 0, *cl1 = 0, *eidx2 = 0, *cl2 = 0;
    int c75 = 0, c25 = 0, c192 = 0, c2048 = 0, c30000 = 0;
    for (int i = 0; i < n_in; i++) {
        const void* p = d_in[i];
        switch (in_sizes[i]) {
            case 180000:  x = (const float*)p; break;
            case 1200000: ea = (const float*)p; break;
            case 90000:   pos = (const float*)p; break;
            case 800000:  eidx = (const int*)p; break;
            case 30000:   if (c30000++ == 0) batch = (const int*)p; else cl1 = (const int*)p; break;
            case 200000:  eidx2 = (const int*)p; break;
            case 15000:   cl2 = (const int*)p; break;
            case 75:      if (c75++ == 0) w1a = (const float*)p; else w2a = (const float*)p; break;
            case 25:      if (c25++ == 0) b1a = (const float*)p; else b2a = (const float*)p; break;
            case 4800:    w1b = (const float*)p; break;
            case 192:     if (c192++ == 0) b1b = (const float*)p; else root1 = (const float*)p; break;
            case 32:      bias1 = (const float*)p; break;
            case 51200:   w2b = (const float*)p; break;
            case 2048:    if (c2048++ == 0) b2b = (const float*)p; else root2 = (const float*)p; break;
            case 64:      bias2 = (const float*)p; break;
            case 8192:    fc1w = (const float*)p; break;
            case 128:     fc1b = (const float*)p; break;
            case 1280:    fc2w = (const float*)p; break;
            case 10:      fc2b = (const float*)p; break;
            default: break;
        }
    }
    float* out = (float*)d_out;

    int cnt1_off_bytes;  // (unused; offsets are device symbols)
    (void)cnt1_off_bytes; (void)out_size;

    // device-symbol pointers needed for k_scan args
    int *p_cnt1, *p_off1, *p_cur1, *p_cnt2, *p_off2, *p_cur2;
    cudaGetSymbolAddress((void**)&p_cnt1, g_cnt_dst1);
    cudaGetSymbolAddress((void**)&p_off1, g_off1);
    cudaGetSymbolAddress((void**)&p_cur1, g_cur1);
    cudaGetSymbolAddress((void**)&p_cnt2, g_cnt_dst2);
    cudaGetSymbolAddress((void**)&p_off2, g_off2);
    cudaGetSymbolAddress((void**)&p_cur2, g_cur2);

    k_zero<<<512, 256>>>();
    k_count<<<512, 256>>>(eidx, eidx2, cl1, batch, pos);
    k_scan<<<1, 1024>>>(p_cnt1, p_off1, p_cur1, NN);
    k_scan<<<1, 1024>>>(p_cnt2, p_off2, p_cur2, C1N);
    k_fill<<<512, 256>>>(eidx, eidx2);
    k_repack<<<64, 256>>>(w1b, b1b, root1, w2b, b2b, root2);
    k_conv1<<<(NN * 32 + 255) / 256, 256>>>(x, ea, eidx, w1a, b1a);
    k_gemm1<<<((NN + 3) / 4 * 32 + 255) / 256, 256>>>(bias1, cl1);
    k_pool1fin<<<512, 256>>>(cl2);
    k_cart<<<(E2N + 255) / 256, 256>>>(eidx2);
    k_conv2<<<(C1N * 32 + 255) / 256, 256>>>(eidx2, w2a, b2a);
    k_gemm2<<<((C1N + 3) / 4 * 32 + 255) / 256, 256>>>(bias2, cl2);
    k_pool2<<<512, 256>>>();
    k_head<<<1, 256>>>(fc1w, fc1b, fc2w, fc2b, out);
}

// round 5
// speedup vs baseline: 1.2260x; 1.2260x over previous
#include <cuda_runtime.h>
#include <math.h>

#define NN   30000
#define E1   400000
#define C1N  15000
#define E2N  100000
#define C2N  7500
#define NBAT 16

// ---------------- scratch (__device__ globals; no dynamic alloc) ----------------
__device__ int      g_cnt_dst1[NN];
__device__ int      g_off1[NN];
__device__ int      g_cur1[NN];
__device__ int      g_elist1[E1];
__device__ int      g_cnt_c1[C1N];
__device__ int      g_cnt_dst2[C1N];
__device__ int      g_off2[C1N];
__device__ int      g_cur2[C1N];
__device__ int      g_elist2[E2N];
__device__ float    g_possum[C1N * 3];
__device__ int      g_batchp[C1N];
__device__ unsigned g_xp_u[C1N * 32];
__device__ float    g_xp[C1N * 32];
__device__ float    g_W1p[162 * 32];
__device__ float    g_cart[E2N * 3];
__device__ unsigned g_absmax;
__device__ float    g_A2[C1N * 864];
__device__ float    g_W2p[864 * 64];
__device__ unsigned g_x3_u[C2N * 64];
__device__ int      g_batch2[C2N];
__device__ float    g_gsum[NBAT * 64];
__device__ int      g_cntb[NBAT];

// order-preserving float <-> uint so atomicMax works; 0u == "empty" decodes to 0.0f
__device__ __forceinline__ unsigned fenc(float f) {
    unsigned u = __float_as_uint(f);
    return (u & 0x80000000u) ? ~u : (u | 0x80000000u);
}
__device__ __forceinline__ float fdec(unsigned u) {
    if (u == 0u) return 0.f;
    return (u & 0x80000000u) ? __uint_as_float(u & 0x7FFFFFFFu) : __uint_as_float(~u);
}
__device__ __forceinline__ float elu_f(float x) {
    return x > 0.f ? x : (expf(x) - 1.f);
}

// ---------------- init: zero scratch + repack fused weights (independent work) ----------------
__global__ void k_init(const float* __restrict__ w1b, const float* __restrict__ b1b,
                       const float* __restrict__ root1,
                       const float* __restrict__ w2b, const float* __restrict__ b2b,
                       const float* __restrict__ root2) {
    int t = blockIdx.x * blockDim.x + threadIdx.x;
    int S = gridDim.x * blockDim.x;
    for (int i = t; i < C1N * 32; i += S) g_xp_u[i] = 0u;
    for (int i = t; i < C2N * 64; i += S) g_x3_u[i] = 0u;
    for (int i = t; i < C1N * 3;  i += S) g_possum[i] = 0.f;
    for (int i = t; i < NN;       i += S) g_cnt_dst1[i] = 0;
    for (int i = t; i < C1N;      i += S) { g_cnt_c1[i] = 0; g_cnt_dst2[i] = 0; g_batchp[i] = 0; }
    for (int i = t; i < C2N;      i += S) g_batch2[i] = 0;
    for (int i = t; i < NBAT * 64;i += S) g_gsum[i] = 0.f;
    for (int i = t; i < NBAT;     i += S) g_cntb[i] = 0;
    if (t == 0) g_absmax = 0u;
    // W1p[j,o]: j=i*26+k (i<6,k<26): k<25 -> w1b[k, i*32+o], k==25 -> b1b[i*32+o];
    //           j in [156,162): root1[j-156, o]
    for (int idx = t; idx < 162 * 32; idx += S) {
        int j = idx >> 5, o = idx & 31;
        float v;
        if (j < 156) {
            int i = j / 26, k = j % 26;
            v = (k < 25) ? w1b[k * 192 + i * 32 + o] : b1b[i * 32 + o];
        } else {
            v = root1[(j - 156) * 32 + o];
        }
        g_W1p[idx] = v;
    }
    // W2p[j,o]: j=k*32+i (k<26,i<32): k<25 -> w2b[k, i*64+o], k==25 -> b2b[i*64+o];
    //           j in [832,864): root2[j-832, o]
    for (int idx = t; idx < 864 * 64; idx += S) {
        int j = idx >> 6, o = idx & 63;
        float v;
        if (j < 832) {
            int k = j >> 5, i = j & 31;
            v = (k < 25) ? w2b[k * 2048 + i * 64 + o] : b2b[i * 64 + o];
        } else {
            v = root2[(j - 832) * 64 + o];
        }
        g_W2p[idx] = v;
    }
}

// ---------------- degree counts + pos-sum + batchp ----------------
__global__ void k_count(const int* __restrict__ eidx, const int* __restrict__ eidx2,
                        const int* __restrict__ cl1, const int* __restrict__ batch,
                        const float* __restrict__ pos) {
    int t = blockIdx.x * blockDim.x + threadIdx.x;
    int S = gridDim.x * blockDim.x;
    for (int e = t; e < E1;  e += S) atomicAdd(&g_cnt_dst1[eidx[E1 + e]], 1);
    for (int e = t; e < E2N; e += S) atomicAdd(&g_cnt_dst2[eidx2[E2N + e]], 1);
    for (int n = t; n < NN;  n += S) {
        int c = cl1[n];
        atomicAdd(&g_cnt_c1[c], 1);
        atomicAdd(&g_possum[c * 3 + 0], pos[n * 3 + 0]);
        atomicAdd(&g_possum[c * 3 + 1], pos[n * 3 + 1]);
        atomicAdd(&g_possum[c * 3 + 2], pos[n * 3 + 2]);
        atomicMax(&g_batchp[c], batch[n]);
    }
}

// ---------------- parallel exclusive scan (warp-shuffle hierarchy), 2 blocks in one launch ----
__device__ void scan_one(const int* __restrict__ cnt, int* __restrict__ off,
                         int* __restrict__ cur, int n) {
    __shared__ int wsum[32];
    int t = threadIdx.x;
    int lane = t & 31, w = t >> 5;
    int chunk = (n + 1023) / 1024;
    int lo = t * chunk, hi = min(lo + chunk, n);
    int s = 0;
    for (int i = lo; i < hi; i++) s += cnt[i];
    int v = s;
#pragma unroll
    for (int d = 1; d < 32; d <<= 1) {
        int u = __shfl_up_sync(0xffffffffu, v, d);
        if (lane >= d) v += u;
    }
    if (lane == 31) wsum[w] = v;
    __syncthreads();
    if (w == 0) {
        int x = wsum[lane];
#pragma unroll
        for (int d = 1; d < 32; d <<= 1) {
            int u = __shfl_up_sync(0xffffffffu, x, d);
            if (lane >= d) x += u;
        }
        wsum[lane] = x;
    }
    __syncthreads();
    int run = (w ? wsum[w - 1] : 0) + (v - s);
    for (int i = lo; i < hi; i++) { off[i] = run; cur[i] = run; run += cnt[i]; }
}
__global__ void k_scan2() {
    if (blockIdx.x == 0) scan_one(g_cnt_dst1, g_off1, g_cur1, NN);
    else                 scan_one(g_cnt_dst2, g_off2, g_cur2, C1N);
}

// ---------------- fill CSR edge lists ----------------
__global__ void k_fill(const int* __restrict__ eidx, const int* __restrict__ eidx2) {
    int t = blockIdx.x * blockDim.x + threadIdx.x;
    int S = gridDim.x * blockDim.x;
    for (int e = t; e < E1; e += S) {
        int d = eidx[E1 + e];
        int p = atomicAdd(&g_cur1[d], 1);
        g_elist1[p] = e;
    }
    for (int e = t; e < E2N; e += S) {
        int d = eidx2[E2N + e];
        int p = atomicAdd(&g_cur2[d], 1);
        g_elist2[p] = e;
    }
}

// ---------------- conv1 + gemm1 + elu + pool1-max FUSED: one warp per dst node ----------------
__global__ void k_conv1(const float* __restrict__ x, const float* __restrict__ eattr,
                        const int* __restrict__ eidx,
                        const float* __restrict__ w1a, const float* __restrict__ b1a,
                        const float* __restrict__ bias1, const int* __restrict__ cl1) {
    int wg = (blockIdx.x * blockDim.x + threadIdx.x) >> 5;
    int lane = threadIdx.x & 31;
    if (wg >= NN) return;
    int n = wg;
    float wa0 = 0.f, wa1 = 0.f, wa2 = 0.f, ba = 0.f;
    if (lane < 25) { wa0 = w1a[lane]; wa1 = w1a[25 + lane]; wa2 = w1a[50 + lane]; ba = b1a[lane]; }
    int it[5], kt[5]; bool vt[5];
#pragma unroll
    for (int t = 0; t < 5; t++) {
        int f = lane + 32 * t;
        vt[t] = (f < 156);
        int ff = vt[t] ? f : 0;
        it[t] = ff / 26; kt[t] = ff % 26;
    }
    float acc[5] = {0.f, 0.f, 0.f, 0.f, 0.f};
    int off = g_off1[n], deg = g_cnt_dst1[n];
    int e_n = 0, s_n = 0;
    if (deg > 0) { e_n = g_elist1[off]; s_n = eidx[e_n]; }
    for (int q = 0; q < deg; q++) {
        int e = e_n, s = s_n;
        if (q + 1 < deg) { e_n = g_elist1[off + q + 1]; s_n = eidx[e_n]; }  // prefetch
        float xr = (lane < 6) ? x[s * 6 + lane] : 0.f;
        float er = (lane < 3) ? eattr[e * 3 + lane] : 0.f;
        float a0 = __shfl_sync(0xffffffffu, er, 0);
        float a1 = __shfl_sync(0xffffffffu, er, 1);
        float a2 = __shfl_sync(0xffffffffu, er, 2);
        float h;
        if (lane < 25) {
            h = fmaf(a2, wa2, fmaf(a1, wa1, fmaf(a0, wa0, ba)));
            h = h > 0.f ? h : 0.f;
        } else {
            h = (lane == 25) ? 1.f : 0.f;
        }
#pragma unroll
        for (int t = 0; t < 5; t++) {
            float xv = __shfl_sync(0xffffffffu, xr, it[t]);
            float hv = __shfl_sync(0xffffffffu, h, kt[t]);
            if (vt[t]) acc[t] = fmaf(xv, hv, acc[t]);
        }
    }
    float inv = 1.f / (float)max(deg, 1);
#pragma unroll
    for (int t = 0; t < 5; t++) acc[t] *= inv;
    float xself = (lane < 6) ? x[n * 6 + lane] : 0.f;
    // fused GEMM row: out[o=lane] = sum_f row[f] * W1p[f,o] + bias1[o]
    float o_acc = bias1[lane];
#pragma unroll
    for (int t = 0; t < 5; t++) {
#pragma unroll
        for (int l = 0; l < 32; l++) {
            int f = l + 32 * t;
            if (f < 156) {
                float av = __shfl_sync(0xffffffffu, acc[t], l);
                o_acc = fmaf(av, g_W1p[f * 32 + lane], o_acc);
            }
        }
    }
#pragma unroll
    for (int l = 0; l < 6; l++) {
        float av = __shfl_sync(0xffffffffu, xself, l);
        o_acc = fmaf(av, g_W1p[(156 + l) * 32 + lane], o_acc);
    }
    float v = elu_f(o_acc);
    atomicMax(&g_xp_u[cl1[n] * 32 + lane], fenc(v));
}

// ---------------- mid: xp decode + batch2 max + cartesian (from sums) + absmax ----------------
__global__ void k_mid(const int* __restrict__ cl2, const int* __restrict__ eidx2) {
    int t = blockIdx.x * blockDim.x + threadIdx.x;
    int S = gridDim.x * blockDim.x;
    for (int i = t; i < C1N * 32; i += S) g_xp[i] = fdec(g_xp_u[i]);
    for (int c = t; c < C1N; c += S) atomicMax(&g_batch2[cl2[c]], g_batchp[c]);
    float m = 0.f;
    for (int e = t; e < E2N; e += S) {
        int s = eidx2[e], d = eidx2[E2N + e];
        float invs = 1.f / (float)max(g_cnt_c1[s], 1);
        float invd = 1.f / (float)max(g_cnt_c1[d], 1);
#pragma unroll
        for (int c = 0; c < 3; c++) {
            float v = g_possum[s * 3 + c] * invs - g_possum[d * 3 + c] * invd;
            g_cart[e * 3 + c] = v;
            m = fmaxf(m, fabsf(v));
        }
    }
#pragma unroll
    for (int o = 16; o; o >>= 1) m = fmaxf(m, __shfl_xor_sync(0xffffffffu, m, o));
    if ((threadIdx.x & 31) == 0) atomicMax(&g_absmax, __float_as_uint(m));  // m >= 0
}

// ---------------- conv2 edge accumulation: one warp per destination cluster ----------------
__global__ void k_conv2(const int* __restrict__ eidx2,
                        const float* __restrict__ w2a, const float* __restrict__ b2a) {
    int wg = (blockIdx.x * blockDim.x + threadIdx.x) >> 5;
    int lane = threadIdx.x & 31;
    if (wg >= C1N) return;
    int c = wg;
    float wa0 = 0.f, wa1 = 0.f, wa2 = 0.f, ba = 0.f;
    if (lane < 25) { wa0 = w2a[lane]; wa1 = w2a[25 + lane]; wa2 = w2a[50 + lane]; ba = b2a[lane]; }
    float scale = 0.5f / __uint_as_float(g_absmax);
    float acc[26];
#pragma unroll
    for (int k = 0; k < 26; k++) acc[k] = 0.f;
    int off = g_off2[c], deg = g_cnt_dst2[c];
    int e_n = 0, s_n = 0;
    if (deg > 0) { e_n = g_elist2[off]; s_n = eidx2[e_n]; }
    for (int q = 0; q < deg; q++) {
        int e = e_n, s = s_n;
        if (q + 1 < deg) { e_n = g_elist2[off + q + 1]; s_n = eidx2[e_n]; }  // prefetch
        float cr = (lane < 3) ? fmaf(g_cart[e * 3 + lane], scale, 0.5f) : 0.f;
        float a0 = __shfl_sync(0xffffffffu, cr, 0);
        float a1 = __shfl_sync(0xffffffffu, cr, 1);
        float a2 = __shfl_sync(0xffffffffu, cr, 2);
        float h;
        if (lane < 25) {
            h = fmaf(a2, wa2, fmaf(a1, wa1, fmaf(a0, wa0, ba)));
            h = h > 0.f ? h : 0.f;
        } else {
            h = (lane == 25) ? 1.f : 0.f;
        }
        float xv = g_xp[s * 32 + lane];
#pragma unroll
        for (int k = 0; k < 26; k++)
            acc[k] = fmaf(xv, __shfl_sync(0xffffffffu, h, k), acc[k]);
    }
    float inv = 1.f / (float)max(deg, 1);
    float* Arow = &g_A2[c * 864];
#pragma unroll
    for (int k = 0; k < 26; k++) Arow[k * 32 + lane] = acc[k] * inv;
    Arow[832 + lane] = g_xp[c * 32 + lane];
}

// ---------------- GEMM2 [C1,864]@[864,64] + bias2, elu, pool2 atomicMax; 8-row blocking ------
__global__ void k_gemm2(const float* __restrict__ bias2, const int* __restrict__ cl2) {
    int warp = (blockIdx.x * blockDim.x + threadIdx.x) >> 5;
    int lane = threadIdx.x & 31;
    int n0 = warp * 8;
    if (n0 >= C1N) return;
    int nr[8];
#pragma unroll
    for (int r = 0; r < 8; r++) nr[r] = min(n0 + r, C1N - 1);
    float acc0[8], acc1[8];
#pragma unroll
    for (int r = 0; r < 8; r++) { acc0[r] = 0.f; acc1[r] = 0.f; }
    const float2* W2 = (const float2*)g_W2p;
    for (int kc = 0; kc < 864; kc += 32) {
        float a[8];
#pragma unroll
        for (int r = 0; r < 8; r++) a[r] = g_A2[nr[r] * 864 + kc + lane];
#pragma unroll 8
        for (int t = 0; t < 32; t++) {
            float2 w = W2[(kc + t) * 32 + lane];  // cols 2*lane, 2*lane+1
#pragma unroll
            for (int r = 0; r < 8; r++) {
                float av = __shfl_sync(0xffffffffu, a[r], t);
                acc0[r] = fmaf(av, w.x, acc0[r]);
                acc1[r] = fmaf(av, w.y, acc1[r]);
            }
        }
    }
    float b0 = bias2[2 * lane], b1 = bias2[2 * lane + 1];
#pragma unroll
    for (int r = 0; r < 8; r++) {
        int n = n0 + r;
        if (n < C1N) {
            float v0 = elu_f(acc0[r] + b0);
            float v1 = elu_f(acc1[r] + b1);
            int c2 = cl2[n];
            atomicMax(&g_x3_u[c2 * 64 + 2 * lane + 0], fenc(v0));
            atomicMax(&g_x3_u[c2 * 64 + 2 * lane + 1], fenc(v1));
        }
    }
}

// ---------------- pool2 -> per-batch sums via shared staging ----------------
__global__ void k_pool2() {
    __shared__ float sh[NBAT * 64];
    __shared__ int scnt[NBAT];
    int t = threadIdx.x;
    for (int i = t; i < NBAT * 64; i += blockDim.x) sh[i] = 0.f;
    if (t < NBAT) scnt[t] = 0;
    __syncthreads();
    int g = blockIdx.x * blockDim.x + t;
    int S = gridDim.x * blockDim.x;
    for (int idx = g; idx < C2N * 64; idx += S) {
        float v = fdec(g_x3_u[idx]);
        int c2 = idx >> 6, o = idx & 63;
        int b = g_batch2[c2];
        atomicAdd(&sh[b * 64 + o], v);
        if (o == 0) atomicAdd(&scnt[b], 1);
    }
    __syncthreads();
    for (int i = t; i < NBAT * 64; i += blockDim.x)
        if (sh[i] != 0.f) atomicAdd(&g_gsum[i], sh[i]);
    if (t < NBAT && scnt[t]) atomicAdd(&g_cntb[t], scnt[t]);
}

// ---------------- head: mean -> fc1+elu -> fc2 -> log_softmax ----------------
__global__ void k_head(const float* __restrict__ fc1w, const float* __restrict__ fc1b,
                       const float* __restrict__ fc2w, const float* __restrict__ fc2b,
                       float* __restrict__ out) {
    __shared__ float sg[16 * 64];
    __shared__ float sh[16 * 128];
    __shared__ float sl[16 * 10];
    int t = threadIdx.x;
    for (int i = t; i < 16 * 64; i += 256) {
        int b = i >> 6;
        sg[i] = g_gsum[i] / (float)max(g_cntb[b], 1);
    }
    __syncthreads();
    for (int i = t; i < 16 * 128; i += 256) {
        int b = i >> 7, j = i & 127;
        float a = fc1b[j];
        for (int q = 0; q < 64; q++) a = fmaf(sg[b * 64 + q], fc1w[q * 128 + j], a);
        sh[i] = elu_f(a);
    }
    __syncthreads();
    for (int i = t; i < 160; i += 256) {
        int b = i / 10, j = i % 10;
        float a = fc2b[j];
        for (int q = 0; q < 128; q++) a = fmaf(sh[b * 128 + q], fc2w[q * 10 + j], a);
        sl[i] = a;
    }
    __syncthreads();
    if (t < 16) {
        float m = -1e30f;
        for (int j = 0; j < 10; j++) m = fmaxf(m, sl[t * 10 + j]);
        float s = 0.f;
        for (int j = 0; j < 10; j++) s += expf(sl[t * 10 + j] - m);
        float lse = logf(s);
        for (int j = 0; j < 10; j++) out[t * 10 + j] = sl[t * 10 + j] - m - lse;
    }
}

// ---------------- host launch ----------------
extern "C" void kernel_launch(void* const* d_in, const int* in_sizes, int n_in,
                              void* d_out, int out_size) {
    const float *x = 0, *ea = 0, *pos = 0, *w1a = 0, *b1a = 0, *w1b = 0, *b1b = 0,
                *root1 = 0, *bias1 = 0, *w2a = 0, *b2a = 0, *w2b = 0, *b2b = 0,
                *root2 = 0, *bias2 = 0, *fc1w = 0, *fc1b = 0, *fc2w = 0, *fc2b = 0;
    const int *eidx = 0, *batch = 0, *cl1 = 0, *eidx2 = 0, *cl2 = 0;
    int c75 = 0, c25 = 0, c192 = 0, c2048 = 0, c30000 = 0;
    for (int i = 0; i < n_in; i++) {
        const void* p = d_in[i];
        switch (in_sizes[i]) {
            case 180000:  x = (const float*)p; break;
            case 1200000: ea = (const float*)p; break;
            case 90000:   pos = (const float*)p; break;
            case 800000:  eidx = (const int*)p; break;
            case 30000:   if (c30000++ == 0) batch = (const int*)p; else cl1 = (const int*)p; break;
            case 200000:  eidx2 = (const int*)p; break;
            case 15000:   cl2 = (const int*)p; break;
            case 75:      if (c75++ == 0) w1a = (const float*)p; else w2a = (const float*)p; break;
            case 25:      if (c25++ == 0) b1a = (const float*)p; else b2a = (const float*)p; break;
            case 4800:    w1b = (const float*)p; break;
            case 192:     if (c192++ == 0) b1b = (const float*)p; else root1 = (const float*)p; break;
            case 32:      bias1 = (const float*)p; break;
            case 51200:   w2b = (const float*)p; break;
            case 2048:    if (c2048++ == 0) b2b = (const float*)p; else root2 = (const float*)p; break;
            case 64:      bias2 = (const float*)p; break;
            case 8192:    fc1w = (const float*)p; break;
            case 128:     fc1b = (const float*)p; break;
            case 1280:    fc2w = (const float*)p; break;
            case 10:      fc2b = (const float*)p; break;
            default: break;
        }
    }
    float* out = (float*)d_out;
    (void)out_size;

    k_init<<<256, 256>>>(w1b, b1b, root1, w2b, b2b, root2);
    k_count<<<512, 256>>>(eidx, eidx2, cl1, batch, pos);
    k_scan2<<<2, 1024>>>();
    k_fill<<<512, 256>>>(eidx, eidx2);
    k_conv1<<<(NN * 32 + 255) / 256, 256>>>(x, ea, eidx, w1a, b1a, bias1, cl1);
    k_mid<<<256, 256>>>(cl2, eidx2);
    k_conv2<<<(C1N * 32 + 255) / 256, 256>>>(eidx2, w2a, b2a);
    k_gemm2<<<((C1N + 7) / 8 * 32 + 255) / 256, 256>>>(bias2, cl2);
    k_pool2<<<120, 256>>>();
    k_head<<<1, 256>>>(fc1w, fc1b, fc2w, fc2b, out);
}

// round 6
// speedup vs baseline: 1.3039x; 1.0636x over previous
#include <cuda_runtime.h>
#include <math.h>

#define NN   30000
#define E1   400000
#define C1N  15000
#define E2N  100000
#define C2N  7500
#define NBAT 16

typedef unsigned long long u64;

// ---------------- scratch (__device__ globals; no dynamic alloc) ----------------
__device__ int      g_cnt_dst1[NN];
__device__ int      g_off1[NN];
__device__ int      g_cur1[NN];
__device__ float4   g_ep1[E1];      // per-edge payload: {src, ea0, ea1, ea2}
__device__ int      g_cnt_c1[C1N];
__device__ int      g_cnt_dst2[C1N];
__device__ int      g_off2[C1N];
__device__ int      g_cur2[C1N];
__device__ float4   g_ep2[E2N];     // per-edge payload: {src, cart0, cart1, cart2}
__device__ float    g_possum[C1N * 3];
__device__ int      g_batchp[C1N];
__device__ unsigned g_xp_u[C1N * 32];
__device__ float    g_xp[C1N * 32];
__device__ float    g_W1p[162 * 32];
__device__ unsigned g_absmax;
__device__ float    g_A2[C1N * 864];
__device__ float    g_W2p[864 * 64];
__device__ unsigned g_x3_u[C2N * 64];
__device__ int      g_batch2[C2N];
__device__ float    g_gsum[NBAT * 64];
__device__ int      g_cntb[NBAT];

// packed f32x2 helpers (FFMA2 path — PTX-only, doubles fp32 FMA throughput)
__device__ __forceinline__ u64 pk(float lo, float hi) {
    u64 r; asm("mov.b64 %0,{%1,%2};" : "=l"(r) : "f"(lo), "f"(hi)); return r;
}
__device__ __forceinline__ void upk(u64 v, float& lo, float& hi) {
    asm("mov.b64 {%0,%1},%2;" : "=f"(lo), "=f"(hi) : "l"(v));
}
__device__ __forceinline__ u64 fma2(u64 a, u64 b, u64 c) {
    u64 d; asm("fma.rn.f32x2 %0,%1,%2,%3;" : "=l"(d) : "l"(a), "l"(b), "l"(c)); return d;
}

// order-preserving float <-> uint so atomicMax works; 0u == "empty" decodes to 0.0f
__device__ __forceinline__ unsigned fenc(float f) {
    unsigned u = __float_as_uint(f);
    return (u & 0x80000000u) ? ~u : (u | 0x80000000u);
}
__device__ __forceinline__ float fdec(unsigned u) {
    if (u == 0u) return 0.f;
    return (u & 0x80000000u) ? __uint_as_float(u & 0x7FFFFFFFu) : __uint_as_float(~u);
}
__device__ __forceinline__ float elu_f(float x) {
    return x > 0.f ? x : (expf(x) - 1.f);
}

// ---------------- init: zero scratch + repack fused weights ----------------
__global__ void k_init(const float* __restrict__ w1b, const float* __restrict__ b1b,
                       const float* __restrict__ root1,
                       const float* __restrict__ w2b, const float* __restrict__ b2b,
                       const float* __restrict__ root2) {
    int t = blockIdx.x * blockDim.x + threadIdx.x;
    int S = gridDim.x * blockDim.x;
    for (int i = t; i < C1N * 32; i += S) g_xp_u[i] = 0u;
    for (int i = t; i < C2N * 64; i += S) g_x3_u[i] = 0u;
    for (int i = t; i < C1N * 3;  i += S) g_possum[i] = 0.f;
    for (int i = t; i < NN;       i += S) g_cnt_dst1[i] = 0;
    for (int i = t; i < C1N;      i += S) { g_cnt_c1[i] = 0; g_cnt_dst2[i] = 0; g_batchp[i] = 0; }
    for (int i = t; i < C2N;      i += S) g_batch2[i] = 0;
    for (int i = t; i < NBAT * 64;i += S) g_gsum[i] = 0.f;
    for (int i = t; i < NBAT;     i += S) g_cntb[i] = 0;
    if (t == 0) g_absmax = 0u;
    // W1p[j,o]: j=i*26+k (i<6,k<26): k<25 -> w1b[k, i*32+o], k==25 -> b1b[i*32+o];
    //           j in [156,162): root1[j-156, o]
    for (int idx = t; idx < 162 * 32; idx += S) {
        int j = idx >> 5, o = idx & 31;
        float v;
        if (j < 156) {
            int i = j / 26, k = j % 26;
            v = (k < 25) ? w1b[k * 192 + i * 32 + o] : b1b[i * 32 + o];
        } else {
            v = root1[(j - 156) * 32 + o];
        }
        g_W1p[idx] = v;
    }
    // W2p[j,o]: j=k*32+i (k<26,i<32): k<25 -> w2b[k, i*64+o], k==25 -> b2b[i*64+o];
    //           j in [832,864): root2[j-832, o]
    for (int idx = t; idx < 864 * 64; idx += S) {
        int j = idx >> 6, o = idx & 63;
        float v;
        if (j < 832) {
            int k = j >> 5, i = j & 31;
            v = (k < 25) ? w2b[k * 2048 + i * 64 + o] : b2b[i * 64 + o];
        } else {
            v = root2[(j - 832) * 64 + o];
        }
        g_W2p[idx] = v;
    }
}

// ---------------- degree counts + pos-sum + batchp ----------------
__global__ void k_count(const int* __restrict__ eidx, const int* __restrict__ eidx2,
                        const int* __restrict__ cl1, const int* __restrict__ batch,
                        const float* __restrict__ pos) {
    int t = blockIdx.x * blockDim.x + threadIdx.x;
    int S = gridDim.x * blockDim.x;
    for (int e = t; e < E1;  e += S) atomicAdd(&g_cnt_dst1[eidx[E1 + e]], 1);
    for (int e = t; e < E2N; e += S) atomicAdd(&g_cnt_dst2[eidx2[E2N + e]], 1);
    for (int n = t; n < NN;  n += S) {
        int c = cl1[n];
        atomicAdd(&g_cnt_c1[c], 1);
        atomicAdd(&g_possum[c * 3 + 0], pos[n * 3 + 0]);
        atomicAdd(&g_possum[c * 3 + 1], pos[n * 3 + 1]);
        atomicAdd(&g_possum[c * 3 + 2], pos[n * 3 + 2]);
        atomicMax(&g_batchp[c], batch[n]);
    }
}

// ---------------- scan (2 blocks) + pos-mean/batch2 (block 2), one launch ----------------
__device__ void scan_one(const int* __restrict__ cnt, int* __restrict__ off,
                         int* __restrict__ cur, int n) {
    __shared__ int wsum[32];
    int t = threadIdx.x;
    int lane = t & 31, w = t >> 5;
    int chunk = (n + 1023) / 1024;
    int lo = t * chunk, hi = min(lo + chunk, n);
    int s = 0;
    for (int i = lo; i < hi; i++) s += cnt[i];
    int v = s;
#pragma unroll
    for (int d = 1; d < 32; d <<= 1) {
        int u = __shfl_up_sync(0xffffffffu, v, d);
        if (lane >= d) v += u;
    }
    if (lane == 31) wsum[w] = v;
    __syncthreads();
    if (w == 0) {
        int x = wsum[lane];
#pragma unroll
        for (int d = 1; d < 32; d <<= 1) {
            int u = __shfl_up_sync(0xffffffffu, x, d);
            if (lane >= d) x += u;
        }
        wsum[lane] = x;
    }
    __syncthreads();
    int run = (w ? wsum[w - 1] : 0) + (v - s);
    for (int i = lo; i < hi; i++) { off[i] = run; cur[i] = run; run += cnt[i]; }
}
__global__ void k_scan2(const int* __restrict__ cl2) {
    if (blockIdx.x == 0) scan_one(g_cnt_dst1, g_off1, g_cur1, NN);
    else if (blockIdx.x == 1) scan_one(g_cnt_dst2, g_off2, g_cur2, C1N);
    else {
        // possum -> mean (in place) + batch2 = segmax(batchp by cl2)
        for (int c = threadIdx.x; c < C1N; c += blockDim.x) {
            float inv = 1.f / (float)max(g_cnt_c1[c], 1);
            g_possum[c * 3 + 0] *= inv;
            g_possum[c * 3 + 1] *= inv;
            g_possum[c * 3 + 2] *= inv;
            atomicMax(&g_batch2[cl2[c]], g_batchp[c]);
        }
    }
}

// ---------------- fill CSR edge payloads (+ cartesian + absmax for level 2) ----------------
__global__ void k_fill(const int* __restrict__ eidx, const float* __restrict__ ea,
                       const int* __restrict__ eidx2) {
    int t = blockIdx.x * blockDim.x + threadIdx.x;
    int S = gridDim.x * blockDim.x;
    for (int e = t; e < E1; e += S) {
        int s = eidx[e], d = eidx[E1 + e];
        int p = atomicAdd(&g_cur1[d], 1);
        g_ep1[p] = make_float4(__int_as_float(s), ea[e * 3 + 0], ea[e * 3 + 1], ea[e * 3 + 2]);
    }
    float m = 0.f;
    for (int e = t; e < E2N; e += S) {
        int s = eidx2[e], d = eidx2[E2N + e];
        float c0 = g_possum[s * 3 + 0] - g_possum[d * 3 + 0];
        float c1 = g_possum[s * 3 + 1] - g_possum[d * 3 + 1];
        float c2 = g_possum[s * 3 + 2] - g_possum[d * 3 + 2];
        int p = atomicAdd(&g_cur2[d], 1);
        g_ep2[p] = make_float4(__int_as_float(s), c0, c1, c2);
        m = fmaxf(m, fmaxf(fabsf(c0), fmaxf(fabsf(c1), fabsf(c2))));
    }
#pragma unroll
    for (int o = 16; o; o >>= 1) m = fmaxf(m, __shfl_xor_sync(0xffffffffu, m, o));
    if ((threadIdx.x & 31) == 0 && m > 0.f) atomicMax(&g_absmax, __float_as_uint(m));
}

// ---------------- conv1 + gemm1 + elu + pool1-max FUSED: one warp per dst node ----------------
// lane = k (h index, valid <26); S[i][k] accumulated as 3 packed f32x2 per lane.
__global__ void k_conv1(const float* __restrict__ x,
                        const float* __restrict__ w1a, const float* __restrict__ b1a,
                        const float* __restrict__ bias1, const int* __restrict__ cl1) {
    int wg = (blockIdx.x * blockDim.x + threadIdx.x) >> 5;
    int lane = threadIdx.x & 31;
    if (wg >= NN) return;
    int n = wg;
    float wa0 = 0.f, wa1 = 0.f, wa2 = 0.f, ba = 0.f;
    if (lane < 25) { wa0 = w1a[lane]; wa1 = w1a[25 + lane]; wa2 = w1a[50 + lane]; ba = b1a[lane]; }
    u64 acc0 = 0, acc1 = 0, acc2 = 0;
    int off = g_off1[n], deg = g_cnt_dst1[n];
    const float4* ep = &g_ep1[off];
    for (int q = 0; q < deg; q++) {
        float4 p = ep[q];                       // uniform broadcast load
        int s = __float_as_int(p.x);
        float h;
        if (lane < 25) {
            h = fmaf(p.w, wa2, fmaf(p.z, wa1, fmaf(p.y, wa0, ba)));
            h = fmaxf(h, 0.f);
        } else {
            h = (lane == 25) ? 1.f : 0.f;
        }
        u64 hh = pk(h, h);
        const u64* xr = (const u64*)(x + s * 6);  // uniform broadcast, 8B-aligned
        acc0 = fma2(xr[0], hh, acc0);
        acc1 = fma2(xr[1], hh, acc1);
        acc2 = fma2(xr[2], hh, acc2);
    }
    float inv = 1.f / (float)max(deg, 1);
    float sv[6];
    upk(acc0, sv[0], sv[1]); upk(acc1, sv[2], sv[3]); upk(acc2, sv[4], sv[5]);
#pragma unroll
    for (int i = 0; i < 6; i++) sv[i] *= inv;
    // fused GEMM row: out[o=lane] = sum_{i,k} S[i][k] * W1p[(i*26+k)*32+o] + self + bias
    float o_acc = bias1[lane];
#pragma unroll
    for (int i = 0; i < 6; i++) {
        float si = sv[i];
#pragma unroll
        for (int k = 0; k < 26; k++) {
            float av = __shfl_sync(0xffffffffu, si, k);
            o_acc = fmaf(av, g_W1p[(i * 26 + k) * 32 + lane], o_acc);
        }
    }
    const u64* xs = (const u64*)(x + n * 6);
    float x0, x1, x2, x3, x4, x5;
    upk(xs[0], x0, x1); upk(xs[1], x2, x3); upk(xs[2], x4, x5);
    o_acc = fmaf(x0, g_W1p[156 * 32 + lane], o_acc);
    o_acc = fmaf(x1, g_W1p[157 * 32 + lane], o_acc);
    o_acc = fmaf(x2, g_W1p[158 * 32 + lane], o_acc);
    o_acc = fmaf(x3, g_W1p[159 * 32 + lane], o_acc);
    o_acc = fmaf(x4, g_W1p[160 * 32 + lane], o_acc);
    o_acc = fmaf(x5, g_W1p[161 * 32 + lane], o_acc);
    float v = elu_f(o_acc);
    atomicMax(&g_xp_u[cl1[n] * 32 + lane], fenc(v));
}

// ---------------- decode pooled features ----------------
__global__ void k_dec() {
    int t = blockIdx.x * blockDim.x + threadIdx.x;
    int S = gridDim.x * blockDim.x;
    for (int i = t; i < C1N * 32; i += S) g_xp[i] = fdec(g_xp_u[i]);
}

// ---------------- conv2 edge accumulation: one warp per destination cluster ----------------
// lane = feature i (32); payload is uniform so h needs no attr shuffles.
__global__ void k_conv2(const float* __restrict__ w2a, const float* __restrict__ b2a) {
    int wg = (blockIdx.x * blockDim.x + threadIdx.x) >> 5;
    int lane = threadIdx.x & 31;
    if (wg >= C1N) return;
    int c = wg;
    float wa0 = 0.f, wa1 = 0.f, wa2 = 0.f, ba = 0.f;
    if (lane < 25) { wa0 = w2a[lane]; wa1 = w2a[25 + lane]; wa2 = w2a[50 + lane]; ba = b2a[lane]; }
    float scale = 0.5f / __uint_as_float(g_absmax);
    float acc[26];
#pragma unroll
    for (int k = 0; k < 26; k++) acc[k] = 0.f;
    int off = g_off2[c], deg = g_cnt_dst2[c];
    const float4* ep = &g_ep2[off];
    for (int q = 0; q < deg; q++) {
        float4 p = ep[q];                       // uniform broadcast load
        int s = __float_as_int(p.x);
        float h;
        if (lane < 25) {
            float c0 = fmaf(p.y, scale, 0.5f);
            float c1 = fmaf(p.z, scale, 0.5f);
            float c2 = fmaf(p.w, scale, 0.5f);
            h = fmaf(c2, wa2, fmaf(c1, wa1, fmaf(c0, wa0, ba)));
            h = fmaxf(h, 0.f);
        } else {
            h = (lane == 25) ? 1.f : 0.f;
        }
        float xv = g_xp[s * 32 + lane];         // coalesced 128B
#pragma unroll
        for (int k = 0; k < 26; k++)
            acc[k] = fmaf(xv, __shfl_sync(0xffffffffu, h, k), acc[k]);
    }
    float inv = 1.f / (float)max(deg, 1);
    float* Arow = &g_A2[c * 864];
#pragma unroll
    for (int k = 0; k < 26; k++) Arow[k * 32 + lane] = acc[k] * inv;
    Arow[832 + lane] = g_xp[c * 32 + lane];
}

// ---------------- GEMM2 [C1,864]@[864,64] + bias2, elu, pool2 atomicMax; FFMA2 ----------------
__global__ void k_gemm2(const float* __restrict__ bias2, const int* __restrict__ cl2) {
    int warp = (blockIdx.x * blockDim.x + threadIdx.x) >> 5;
    int lane = threadIdx.x & 31;
    int n0 = warp * 8;
    if (n0 >= C1N) return;
    int nr[8];
#pragma unroll
    for (int r = 0; r < 8; r++) nr[r] = min(n0 + r, C1N - 1);
    u64 accp[8];
#pragma unroll
    for (int r = 0; r < 8; r++) accp[r] = 0;
    for (int kc = 0; kc < 864; kc += 32) {
        float a[8];
#pragma unroll
        for (int r = 0; r < 8; r++) a[r] = g_A2[nr[r] * 864 + kc + lane];
#pragma unroll 8
        for (int t = 0; t < 32; t++) {
            u64 w = *(const u64*)&g_W2p[(kc + t) * 64 + 2 * lane];  // cols 2lane,2lane+1
#pragma unroll
            for (int r = 0; r < 8; r++) {
                float av = __shfl_sync(0xffffffffu, a[r], t);
                accp[r] = fma2(pk(av, av), w, accp[r]);
            }
        }
    }
    float b0 = bias2[2 * lane], b1 = bias2[2 * lane + 1];
#pragma unroll
    for (int r = 0; r < 8; r++) {
        int n = n0 + r;
        if (n < C1N) {
            float a0, a1;
            upk(accp[r], a0, a1);
            float v0 = elu_f(a0 + b0);
            float v1 = elu_f(a1 + b1);
            int c2 = cl2[n];
            atomicMax(&g_x3_u[c2 * 64 + 2 * lane + 0], fenc(v0));
            atomicMax(&g_x3_u[c2 * 64 + 2 * lane + 1], fenc(v1));
        }
    }
}

// ---------------- pool2 -> per-batch sums via shared staging ----------------
__global__ void k_pool2() {
    __shared__ float sh[NBAT * 64];
    __shared__ int scnt[NBAT];
    int t = threadIdx.x;
    for (int i = t; i < NBAT * 64; i += blockDim.x) sh[i] = 0.f;
    if (t < NBAT) scnt[t] = 0;
    __syncthreads();
    int g = blockIdx.x * blockDim.x + t;
    int S = gridDim.x * blockDim.x;
    for (int idx = g; idx < C2N * 64; idx += S) {
        float v = fdec(g_x3_u[idx]);
        int c2 = idx >> 6, o = idx & 63;
        int b = g_batch2[c2];
        atomicAdd(&sh[b * 64 + o], v);
        if (o == 0) atomicAdd(&scnt[b], 1);
    }
    __syncthreads();
    for (int i = t; i < NBAT * 64; i += blockDim.x)
        if (sh[i] != 0.f) atomicAdd(&g_gsum[i], sh[i]);
    if (t < NBAT && scnt[t]) atomicAdd(&g_cntb[t], scnt[t]);
}

// ---------------- head: mean -> fc1+elu -> fc2 -> log_softmax ----------------
__global__ void k_head(const float* __restrict__ fc1w, const float* __restrict__ fc1b,
                       const float* __restrict__ fc2w, const float* __restrict__ fc2b,
                       float* __restrict__ out) {
    __shared__ float sg[16 * 64];
    __shared__ float sh[16 * 128];
    __shared__ float sl[16 * 10];
    int t = threadIdx.x;
    for (int i = t; i < 16 * 64; i += 256) {
        int b = i >> 6;
        sg[i] = g_gsum[i] / (float)max(g_cntb[b], 1);
    }
    __syncthreads();
    for (int i = t; i < 16 * 128; i += 256) {
        int b = i >> 7, j = i & 127;
        float a = fc1b[j];
        for (int q = 0; q < 64; q++) a = fmaf(sg[b * 64 + q], fc1w[q * 128 + j], a);
        sh[i] = elu_f(a);
    }
    __syncthreads();
    for (int i = t; i < 160; i += 256) {
        int b = i / 10, j = i % 10;
        float a = fc2b[j];
        for (int q = 0; q < 128; q++) a = fmaf(sh[b * 128 + q], fc2w[q * 10 + j], a);
        sl[i] = a;
    }
    __syncthreads();
    if (t < 16) {
        float m = -1e30f;
        for (int j = 0; j < 10; j++) m = fmaxf(m, sl[t * 10 + j]);
        float s = 0.f;
        for (int j = 0; j < 10; j++) s += expf(sl[t * 10 + j] - m);
        float lse = logf(s);
        for (int j = 0; j < 10; j++) out[t * 10 + j] = sl[t * 10 + j] - m - lse;
    }
}

// ---------------- host launch ----------------
extern "C" void kernel_launch(void* const* d_in, const int* in_sizes, int n_in,
                              void* d_out, int out_size) {
    const float *x = 0, *ea = 0, *pos = 0, *w1a = 0, *b1a = 0, *w1b = 0, *b1b = 0,
                *root1 = 0, *bias1 = 0, *w2a = 0, *b2a = 0, *w2b = 0, *b2b = 0,
                *root2 = 0, *bias2 = 0, *fc1w = 0, *fc1b = 0, *fc2w = 0, *fc2b = 0;
    const int *eidx = 0, *batch = 0, *cl1 = 0, *eidx2 = 0, *cl2 = 0;
    int c75 = 0, c25 = 0, c192 = 0, c2048 = 0, c30000 = 0;
    for (int i = 0; i < n_in; i++) {
        const void* p = d_in[i];
        switch (in_sizes[i]) {
            case 180000:  x = (const float*)p; break;
            case 1200000: ea = (const float*)p; break;
            case 90000:   pos = (const float*)p; break;
            case 800000:  eidx = (const int*)p; break;
            case 30000:   if (c30000++ == 0) batch = (const int*)p; else cl1 = (const int*)p; break;
            case 200000:  eidx2 = (const int*)p; break;
            case 15000:   cl2 = (const int*)p; break;
            case 75:      if (c75++ == 0) w1a = (const float*)p; else w2a = (const float*)p; break;
            case 25:      if (c25++ == 0) b1a = (const float*)p; else b2a = (const float*)p; break;
            case 4800:    w1b = (const float*)p; break;
            case 192:     if (c192++ == 0) b1b = (const float*)p; else root1 = (const float*)p; break;
            case 32:      bias1 = (const float*)p; break;
            case 51200:   w2b = (const float*)p; break;
            case 2048:    if (c2048++ == 0) b2b = (const float*)p; else root2 = (const float*)p; break;
            case 64:      bias2 = (const float*)p; break;
            case 8192:    fc1w = (const float*)p; break;
            case 128:     fc1b = (const float*)p; break;
            case 1280:    fc2w = (const float*)p; break;
            case 10:      fc2b = (const float*)p; break;
            default: break;
        }
    }
    float* out = (float*)d_out;
    (void)out_size; (void)pos;

    k_init<<<256, 256>>>(w1b, b1b, root1, w2b, b2b, root2);
    k_count<<<512, 256>>>(eidx, eidx2, cl1, batch, pos);
    k_scan2<<<3, 1024>>>(cl2);
    k_fill<<<1024, 256>>>(eidx, ea, eidx2);
    k_conv1<<<(NN * 32 + 255) / 256, 256>>>(x, w1a, b1a, bias1, cl1);
    k_dec<<<256, 256>>>();
    k_conv2<<<(C1N * 32 + 255) / 256, 256>>>(w2a, b2a);
    k_gemm2<<<((C1N + 7) / 8 * 32 + 255) / 256, 256>>>(bias2, cl2);
    k_pool2<<<120, 256>>>();
    k_head<<<1, 256>>>(fc1w, fc1b, fc2w, fc2b, out);
}